// round 10
// baseline (speedup 1.0000x reference)
#include <cuda_runtime.h>
#include <cstdint>

#define DIMN 32
#define TPB 256
#define STAGES 4

__device__ __forceinline__ unsigned long long pack2(float lo, float hi) {
    unsigned long long r;
    asm("mov.b64 %0, {%1, %2};" : "=l"(r) : "f"(lo), "f"(hi));
    return r;
}
__device__ __forceinline__ void unpack2(unsigned long long v, float& lo, float& hi) {
    asm("mov.b64 {%0, %1}, %2;" : "=f"(lo), "=f"(hi) : "l"(v));
}
__device__ __forceinline__ unsigned long long fma2(unsigned long long a,
                                                   unsigned long long b,
                                                   unsigned long long c) {
    unsigned long long d;
    asm("fma.rn.f32x2 %0, %1, %2, %3;" : "=l"(d) : "l"(a), "l"(b), "l"(c));
    return d;
}

__device__ __forceinline__ void cp_async16(void* smem_dst, const void* gmem_src) {
    uint32_t sa = (uint32_t)__cvta_generic_to_shared(smem_dst);
    asm volatile("cp.async.cg.shared.global [%0], [%1], 16;"
                 :: "r"(sa), "l"(gmem_src) : "memory");
}
__device__ __forceinline__ void cp_commit() {
    asm volatile("cp.async.commit_group;" ::: "memory");
}
template <int N>
__device__ __forceinline__ void cp_wait() {
    asm volatile("cp.async.wait_group %0;" :: "n"(N) : "memory");
}

__global__ __launch_bounds__(TPB) void poly_cpasync_kernel(
    const float* __restrict__ x,
    const float* __restrict__ w,
    float* __restrict__ out,
    int n_vec4,
    int n_tiles)
{
    __shared__ __align__(16) float4 s_x[STAGES][TPB];
    __shared__ unsigned long long s_wp[DIMN];

    const float4* __restrict__ x4 = reinterpret_cast<const float4*>(x);
    float4* __restrict__ o4 = reinterpret_cast<float4*>(out);
    const int tid = threadIdx.x;
    const int grid = gridDim.x;

    // ---- prologue: start STAGES tile fills immediately (deep MLP, no regs) ----
#pragma unroll
    for (int s = 0; s < STAGES; ++s) {
        int t = blockIdx.x + s * grid;
        if (t < n_tiles)
            cp_async16(&s_x[s][tid], x4 + (size_t)t * TPB + tid);
        cp_commit();  // one group per stage, even if empty
    }

    // ---- pack coefficients into smem (fused; no separate kernel) ----
    if (tid < DIMN) {
        float wk = __ldg(&w[tid]);
        s_wp[tid] = pack2(wk, wk);
    }
    __syncthreads();

    int trip = 0;
    for (int t = blockIdx.x; t < n_tiles; t += grid, ++trip) {
        cp_wait<STAGES - 1>();           // oldest group (this trip's tile) done
        int slot = trip & (STAGES - 1);
        float4 xv = s_x[slot][tid];      // thread-private slot: no barrier needed

        // Opaque pointer: stop ptxas hoisting 32 u64 coefficients into regs.
        const unsigned long long* wp = s_wp;
        asm("" : "+l"(wp));

        unsigned long long p0 = pack2(xv.x, xv.y);
        unsigned long long p1 = pack2(xv.z, xv.w);
        unsigned long long a0 = wp[DIMN - 1];
        unsigned long long a1 = a0;

#pragma unroll
        for (int k = DIMN - 2; k >= 0; --k) {
            unsigned long long wk = wp[k];   // broadcast LDS.64 feeds 2 FFMA2
            a0 = fma2(a0, p0, wk);
            a1 = fma2(a1, p1, wk);
        }

        float4 ov;
        unpack2(a0, ov.x, ov.y);
        unpack2(a1, ov.z, ov.w);
        o4[(size_t)t * TPB + tid] = ov;

        // Refill this slot with tile t + STAGES*grid (issued ~3 tiles ahead).
        int tn = t + STAGES * grid;
        if (tn < n_tiles)
            cp_async16(&s_x[slot][tid], x4 + (size_t)tn * TPB + tid);
        cp_commit();
    }
}

extern "C" void kernel_launch(void* const* d_in, const int* in_sizes, int n_in,
                              void* d_out, int out_size) {
    const float* x = (const float*)d_in[0];
    const float* w = (const float*)d_in[1];
    float* out = (float*)d_out;

    int n = in_sizes[0];                  // 4194304
    int n_vec4 = n / 4;                   // 1048576 float4s
    int n_tiles = (n_vec4 + TPB - 1) / TPB;   // 4096 tiles of 256 float4s

    int sms = 148;
    cudaDeviceGetAttribute(&sms, cudaDevAttrMultiProcessorCount, 0);
    int blocks = sms * 4;                 // ~7 tiles/block, 4 blocks/SM resident
    if (blocks > n_tiles) blocks = n_tiles;

    poly_cpasync_kernel<<<blocks, TPB>>>(x, w, out, n_vec4, n_tiles);
}

// round 11
// speedup vs baseline: 1.4159x; 1.4159x over previous
#include <cuda_runtime.h>

#define DIMN 32
#define TPB 256

__global__ __launch_bounds__(TPB) void poly_scalar_persist_kernel(
    const float* __restrict__ x,
    const float* __restrict__ w,
    float* __restrict__ out,
    int n_vec4)
{
    const float4* __restrict__ x4 = reinterpret_cast<const float4*>(x);
    float4* __restrict__ o4 = reinterpret_cast<float4*>(out);
    const int tid = threadIdx.x;

    // ---- all 32 coefficients in scalar registers, loaded once ----
#define LDW(i) float w##i = __ldg(&w[i]);
    LDW(0)  LDW(1)  LDW(2)  LDW(3)  LDW(4)  LDW(5)  LDW(6)  LDW(7)
    LDW(8)  LDW(9)  LDW(10) LDW(11) LDW(12) LDW(13) LDW(14) LDW(15)
    LDW(16) LDW(17) LDW(18) LDW(19) LDW(20) LDW(21) LDW(22) LDW(23)
    LDW(24) LDW(25) LDW(26) LDW(27) LDW(28) LDW(29) LDW(30) LDW(31)
#undef LDW

    const int stride = gridDim.x * (2 * TPB);   // float4s per sweep
    int i = blockIdx.x * (2 * TPB) + tid;

    // ---- prologue: first pair of float4s ----
    float4 curA = (i < n_vec4) ? __ldg(&x4[i])
                               : make_float4(0.f, 0.f, 0.f, 0.f);
    float4 curB = (i + TPB < n_vec4) ? __ldg(&x4[i + TPB])
                                     : make_float4(0.f, 0.f, 0.f, 0.f);

    while (i < n_vec4) {
        // ---- prefetch next sweep before the compute burst ----
        int ni = i + stride;
        float4 nxtA = (ni < n_vec4) ? __ldg(&x4[ni])
                                    : make_float4(0.f, 0.f, 0.f, 0.f);
        float4 nxtB = (ni + TPB < n_vec4) ? __ldg(&x4[ni + TPB])
                                          : make_float4(0.f, 0.f, 0.f, 0.f);

        // ---- 8 independent scalar Horner chains (named regs only) ----
        float p0 = curA.x, p1 = curA.y, p2 = curA.z, p3 = curA.w;
        float p4 = curB.x, p5 = curB.y, p6 = curB.z, p7 = curB.w;

        float a0 = w31, a1 = w31, a2 = w31, a3 = w31;
        float a4 = w31, a5 = w31, a6 = w31, a7 = w31;

#define STEP(WK) \
        a0 = fmaf(a0, p0, WK); a1 = fmaf(a1, p1, WK); \
        a2 = fmaf(a2, p2, WK); a3 = fmaf(a3, p3, WK); \
        a4 = fmaf(a4, p4, WK); a5 = fmaf(a5, p5, WK); \
        a6 = fmaf(a6, p6, WK); a7 = fmaf(a7, p7, WK);

        STEP(w30) STEP(w29) STEP(w28) STEP(w27) STEP(w26) STEP(w25)
        STEP(w24) STEP(w23) STEP(w22) STEP(w21) STEP(w20) STEP(w19)
        STEP(w18) STEP(w17) STEP(w16) STEP(w15) STEP(w14) STEP(w13)
        STEP(w12) STEP(w11) STEP(w10) STEP(w9)  STEP(w8)  STEP(w7)
        STEP(w6)  STEP(w5)  STEP(w4)  STEP(w3)  STEP(w2)  STEP(w1)
        STEP(w0)
#undef STEP

        if (i < n_vec4)
            o4[i] = make_float4(a0, a1, a2, a3);
        if (i + TPB < n_vec4)
            o4[i + TPB] = make_float4(a4, a5, a6, a7);

        curA = nxtA;
        curB = nxtB;
        i = ni;
    }
}

extern "C" void kernel_launch(void* const* d_in, const int* in_sizes, int n_in,
                              void* d_out, int out_size) {
    const float* x = (const float*)d_in[0];
    const float* w = (const float*)d_in[1];
    float* out = (float*)d_out;

    int n = in_sizes[0];            // 4194304
    int n_vec4 = n / 4;             // 1048576 float4s

    int sms = 148;
    cudaDeviceGetAttribute(&sms, cudaDevAttrMultiProcessorCount, 0);
    int blocks = sms * 4;           // all resident (regs ~60 -> 4 blocks/SM)
    int max_blocks = (n_vec4 + 2 * TPB - 1) / (2 * TPB);
    if (blocks > max_blocks) blocks = max_blocks;

    poly_scalar_persist_kernel<<<blocks, TPB>>>(x, w, out, n_vec4);
}